// round 12
// baseline (speedup 1.0000x reference)
#include <cuda_runtime.h>
#include <cstdint>

// AttentionalPropagation R11.
//   K0:  x[B,C,L] -> xT[L,B,C]     register 4x4-block transpose (proven, 6.4TB/s)
//   K12: per-l CTA, 512 threads = 4 warp-groups. Group g owns c-chunks
//        4g..4g+3: stages them (cp.async), accumulates partial S, runs pass 2
//        on them with a private msg plane. Partial-S tree-reduction and
//        P-fragment broadcast via smem; softmax + register P-permute verbatim
//        on group 0 (numerically locked since R5, rel_err 2.283e-4).
//   K3:  outT -> out[B,C,L]        register 4x4-block transpose
// R10 finding: K12 is latency-bound at 8 warps/SM; this doubles warps and
// halves per-group phase count.

namespace {

constexpr int kB  = 64;
constexpr int kC  = 512;
constexpr int kL  = 4096;
constexpr int kBC = kB * kC;
constexpr int CCH = 32;
constexpr int NCH = kC / CCH;        // 16
constexpr int NG  = 4;               // warp-groups
constexpr int GCH = NCH / NG;        // 4 chunks per group

constexpr int PR    = 36;            // words per b-row (16B-aligned rows)
constexpr int PLANE = kB * PR;       // 2304 words = 9216 B per chunk plane
constexpr int XW    = 128 * 33;      // exchange buffer: 33 words/thread = 4224
constexpr int SMEM_K12 = (NCH + NG) * PLANE * 4;   // 20 planes = 184320 B
static_assert(2 * XW <= NG * PLANE, "exchange fits in msg-plane region");

__device__ float xT_g[(size_t)kL * kBC];            // 512 MB [L][B][C]
__device__ float oT_g[(size_t)kL * kBC];            // 512 MB [L][B][C]

__device__ __forceinline__ uint32_t fbits(float f) { return __float_as_uint(f); }

__device__ __forceinline__ void mma_tf32(float d[4],
                                         uint32_t a0, uint32_t a1, uint32_t a2, uint32_t a3,
                                         uint32_t b0, uint32_t b1) {
    asm volatile(
        "mma.sync.aligned.m16n8k8.row.col.f32.tf32.tf32.f32 "
        "{%0,%1,%2,%3}, {%4,%5,%6,%7}, {%8,%9}, {%0,%1,%2,%3};"
        : "+f"(d[0]), "+f"(d[1]), "+f"(d[2]), "+f"(d[3])
        : "r"(a0), "r"(a1), "r"(a2), "r"(a3), "r"(b0), "r"(b1));
}

__device__ __forceinline__ void cp16(uint32_t dst, const void* src) {
    asm volatile("cp.async.ca.shared.global [%0], [%1], 16;" :: "r"(dst), "l"(src));
}
__device__ __forceinline__ void cp_commit() {
    asm volatile("cp.async.commit_group;" ::: "memory");
}
template <int N>
__device__ __forceinline__ void cp_wait() {
    asm volatile("cp.async.wait_group %0;" :: "n"(N) : "memory");
}
__device__ __forceinline__ void cp_wait_n(int n) {   // constant-folded call sites
    switch (n) {
        case 0: cp_wait<0>(); break;  case 1: cp_wait<1>(); break;
        case 2: cp_wait<2>(); break;  default: cp_wait<3>(); break;
    }
}
__device__ __forceinline__ void bar_group(int grp) {   // 128-thread named barrier
    asm volatile("bar.sync %0, 128;" :: "r"(grp + 1) : "memory");
}

// ------------- register 4x4-block transpose: dst[c][r] = src[r][c] ----------
__device__ __forceinline__ void transpose_reg(const float* __restrict__ src,
                                              float* __restrict__ dst,
                                              int src_cols, int dst_cols) {
    const int C0 = blockIdx.x * 64;
    const int R0 = blockIdx.y * 64;
    const int t  = threadIdx.x;
    const int bj = t & 15;
    const int bi = t >> 4;

    const float* sp = src + (size_t)(R0 + 4 * bi) * src_cols + C0 + 4 * bj;
    const float4 r0 = *(const float4*)sp;
    const float4 r1 = *(const float4*)(sp + src_cols);
    const float4 r2 = *(const float4*)(sp + 2 * (size_t)src_cols);
    const float4 r3 = *(const float4*)(sp + 3 * (size_t)src_cols);

    float* dp = dst + (size_t)(C0 + 4 * bj) * dst_cols + R0 + 4 * bi;
    *(float4*)dp                          = make_float4(r0.x, r1.x, r2.x, r3.x);
    *(float4*)(dp + dst_cols)             = make_float4(r0.y, r1.y, r2.y, r3.y);
    *(float4*)(dp + 2 * (size_t)dst_cols) = make_float4(r0.z, r1.z, r2.z, r3.z);
    *(float4*)(dp + 3 * (size_t)dst_cols) = make_float4(r0.w, r1.w, r2.w, r3.w);
}

__global__ void __launch_bounds__(256) k0_transpose(const float* __restrict__ x) {
    transpose_reg(x, xT_g, kL, kBC);
}
__global__ void __launch_bounds__(256) k3_transpose(float* __restrict__ out) {
    transpose_reg(oT_g, out, kBC, kL);
}

// -------- chunk staging: xT[l][b][c0..c0+31] -> plane [b][c] pitch 36 -------
__device__ __forceinline__ void issue_chunk(uint32_t smbase, int plane,
                                            int l, int c0, int tg) {
    const int b = tg >> 1, h = tg & 1;
    const float* src = xT_g + ((size_t)(l * kB + b)) * kC + c0 + h * 16;
    const uint32_t dst = smbase + (uint32_t)(plane * PLANE + b * PR + h * 16) * 4u;
    #pragma unroll
    for (int i = 0; i < 4; i++) cp16(dst + 16u * i, src + 4 * i);
}

// ====================== K12: fused scores+softmax+apply =====================
__global__ void __launch_bounds__(512)
k12_fused() {
    extern __shared__ float sm[];
    float* xch = sm + NCH * PLANE;         // 4 planes: exchange, then msg[grp]
    float* X0  = xch;
    float* X1  = xch + XW;

    const int t = threadIdx.x, lane = t & 31;
    const int w = t >> 5;
    const int strip = w & 3;               // 16-row strip of the 64x64 matrix
    const int grp   = w >> 2;              // warp-group: owns chunks 4g..4g+3
    const int tg    = t & 127;             // thread-in-group
    const int l = blockIdx.x;
    const int r0 = lane >> 2, q4 = lane & 3;
    const uint32_t smbase = (uint32_t)__cvta_generic_to_shared(sm);

    // Stage this group's 4 chunks (4 cp.async groups per thread, in order).
    #pragma unroll
    for (int i = 0; i < GCH; i++) {
        const int ch = grp * GCH + i;
        issue_chunk(smbase, ch, l, ch * CCH, tg);
        cp_commit();
    }

    float acc[8][4];
    #pragma unroll
    for (int j = 0; j < 8; j++)
        #pragma unroll
        for (int i = 0; i < 4; i++) acc[j][i] = 0.0f;

    // -------- Pass 1: partial S over this group's chunks (progressive) ------
    #pragma unroll
    for (int i = 0; i < GCH; i++) {
        cp_wait_n(GCH - 1 - i);
        bar_group(grp);
        const float* pl = sm + (grp * GCH + i) * PLANE;
        #pragma unroll
        for (int sk = 0; sk < 4; sk++) {
            const int ca = 8 * sk + q4;
            const float* ap = pl + (strip * 16 + r0) * PR + ca;
            const uint32_t a0 = fbits(ap[0]);
            const uint32_t a1 = fbits(ap[8 * PR]);
            const uint32_t a2 = fbits(ap[4]);
            const uint32_t a3 = fbits(ap[8 * PR + 4]);
            #pragma unroll
            for (int j = 0; j < 8; j++) {
                const float* bp = pl + (8 * j + r0) * PR + ca;
                mma_tf32(acc[j], a0, a1, a2, a3, fbits(bp[0]), fbits(bp[4]));
            }
        }
    }

    // -------- Cross-group tree reduction: S = sum of 4 partials --------------
    __syncthreads();
    if (grp == 1 || grp == 3) {
        float* xp = (grp == 1 ? X0 : X1) + tg * 33;
        #pragma unroll
        for (int j = 0; j < 8; j++)
            #pragma unroll
            for (int i = 0; i < 4; i++) xp[j * 4 + i] = acc[j][i];
    }
    __syncthreads();
    if (grp == 0 || grp == 2) {
        const float* xp = (grp == 0 ? X0 : X1) + tg * 33;
        #pragma unroll
        for (int j = 0; j < 8; j++)
            #pragma unroll
            for (int i = 0; i < 4; i++) acc[j][i] += xp[j * 4 + i];
    }
    __syncthreads();
    if (grp == 2) {
        float* xp = X0 + tg * 33;
        #pragma unroll
        for (int j = 0; j < 8; j++)
            #pragma unroll
            for (int i = 0; i < 4; i++) xp[j * 4 + i] = acc[j][i];
    }
    __syncthreads();

    if (grp == 0) {
        const float* xp = X0 + tg * 33;
        #pragma unroll
        for (int j = 0; j < 8; j++)
            #pragma unroll
            for (int i = 0; i < 4; i++) acc[j][i] += xp[j * 4 + i];

        // ---------------- Softmax (verbatim, warp-local rows) ---------------
        const float isc = 0.044194173824159216f;   // 1/sqrt(512)
        #pragma unroll
        for (int hh = 0; hh < 2; hh++) {
            float mx = -1e30f;
            #pragma unroll
            for (int j = 0; j < 8; j++) {
                acc[j][2 * hh]     *= isc;
                acc[j][2 * hh + 1] *= isc;
                mx = fmaxf(mx, fmaxf(acc[j][2 * hh], acc[j][2 * hh + 1]));
            }
            mx = fmaxf(mx, __shfl_xor_sync(0xffffffffu, mx, 1));
            mx = fmaxf(mx, __shfl_xor_sync(0xffffffffu, mx, 2));
            float ssum = 0.0f;
            #pragma unroll
            for (int j = 0; j < 8; j++) {
                const float e0 = __expf(acc[j][2 * hh] - mx);
                const float e1 = __expf(acc[j][2 * hh + 1] - mx);
                acc[j][2 * hh] = e0; acc[j][2 * hh + 1] = e1;
                ssum += e0 + e1;
            }
            ssum += __shfl_xor_sync(0xffffffffu, ssum, 1);
            ssum += __shfl_xor_sync(0xffffffffu, ssum, 2);
            const float inv = 1.0f / ssum;
            #pragma unroll
            for (int j = 0; j < 8; j++) {
                acc[j][2 * hh] *= inv; acc[j][2 * hh + 1] *= inv;
            }
        }

        // ------ Permute accumulator frags -> A frags of P (verbatim) --------
        const int srcA = (lane & 28) | (q4 >> 1);
        const int srcB = srcA | 2;
        const bool odd = (q4 & 1) != 0;
        #pragma unroll
        for (int sk = 0; sk < 8; sk++) {
            const float v0 = __shfl_sync(0xffffffffu, acc[sk][0], srcA);
            const float v1 = __shfl_sync(0xffffffffu, acc[sk][1], srcA);
            const float v2 = __shfl_sync(0xffffffffu, acc[sk][2], srcA);
            const float v3 = __shfl_sync(0xffffffffu, acc[sk][3], srcA);
            const float w0 = __shfl_sync(0xffffffffu, acc[sk][0], srcB);
            const float w1 = __shfl_sync(0xffffffffu, acc[sk][1], srcB);
            const float w2 = __shfl_sync(0xffffffffu, acc[sk][2], srcB);
            const float w3 = __shfl_sync(0xffffffffu, acc[sk][3], srcB);
            acc[sk][0] = odd ? v1 : v0;    // P[r0][8sk+q4]
            acc[sk][1] = odd ? v3 : v2;    // P[r0+8][8sk+q4]
            acc[sk][2] = odd ? w1 : w0;    // P[r0][8sk+q4+4]
            acc[sk][3] = odd ? w3 : w2;    // P[r0+8][8sk+q4+4]
        }

        // Broadcast P A-frags (tg-indexed: same strip/lane role per group).
        float* xp2 = X0 + tg * 33;
        #pragma unroll
        for (int sk = 0; sk < 8; sk++)
            #pragma unroll
            for (int i = 0; i < 4; i++) xp2[sk * 4 + i] = acc[sk][i];
    }
    __syncthreads();
    if (grp != 0) {
        const float* xp = X0 + tg * 33;
        #pragma unroll
        for (int sk = 0; sk < 8; sk++)
            #pragma unroll
            for (int i = 0; i < 4; i++) acc[sk][i] = xp[sk * 4 + i];
    }
    __syncthreads();                       // exchange done -> msg planes usable

    // -------- Pass 2: outT = xT + P q over this group's chunks --------------
    float* msg = xch + grp * PLANE;
    #pragma unroll 1
    for (int i = 0; i < GCH; i++) {
        const int ch = grp * GCH + i;
        const float* pl = sm + ch * PLANE;

        // Residual preload: out = x + P q via accumulate.
        float macc[4][4];
        #pragma unroll
        for (int j2 = 0; j2 < 4; j2++) {
            const float* xp = pl + (strip * 16 + r0) * PR + 8 * j2 + 2 * q4;
            macc[j2][0] = xp[0];          macc[j2][1] = xp[1];
            macc[j2][2] = xp[8 * PR];     macc[j2][3] = xp[8 * PR + 1];
        }

        #pragma unroll
        for (int sk = 0; sk < 8; sk++) {
            #pragma unroll
            for (int j2 = 0; j2 < 4; j2++) {
                const float* bp = pl + (8 * sk + q4) * PR + 8 * j2 + r0;
                mma_tf32(macc[j2],
                         fbits(acc[sk][0]), fbits(acc[sk][1]),
                         fbits(acc[sk][2]), fbits(acc[sk][3]),
                         fbits(bp[0]), fbits(bp[4 * PR]));
            }
        }

        // msg fragments -> group msg plane [n][c] pitch PR.
        #pragma unroll
        for (int j2 = 0; j2 < 4; j2++) {
            float* mp = msg + (strip * 16 + r0) * PR + 8 * j2 + 2 * q4;
            mp[0] = macc[j2][0];          mp[1] = macc[j2][1];
            mp[8 * PR] = macc[j2][2];     mp[8 * PR + 1] = macc[j2][3];
        }
        bar_group(grp);                    // msg visible within group

        // Epilogue: 64B contiguous per thread to outT.
        {
            const int b = tg >> 1, h = tg & 1;
            const float* mp = msg + b * PR + h * 16;
            float* op = oT_g + ((size_t)(l * kB + b)) * kC + ch * CCH + h * 16;
            #pragma unroll
            for (int k = 0; k < 4; k++)
                ((float4*)op)[k] = make_float4(mp[4 * k], mp[4 * k + 1],
                                               mp[4 * k + 2], mp[4 * k + 3]);
        }
        bar_group(grp);                    // msg drained before next overwrite
    }
}

}  // namespace

extern "C" void kernel_launch(void* const* d_in, const int* in_sizes, int n_in,
                              void* d_out, int out_size) {
    (void)in_sizes; (void)n_in; (void)out_size;
    const float* x = (const float*)d_in[0];
    float* out     = (float*)d_out;

    cudaFuncSetAttribute(k12_fused,
                         cudaFuncAttributeMaxDynamicSharedMemorySize, SMEM_K12);

    dim3 g0(kL / 64, kBC / 64);
    k0_transpose<<<g0, 256>>>(x);
    k12_fused<<<kL, 512, SMEM_K12>>>();
    dim3 g3(kBC / 64, kL / 64);
    k3_transpose<<<g3, 256>>>(out);
}

// round 14
// speedup vs baseline: 1.0912x; 1.0912x over previous
#include <cuda_runtime.h>
#include <cuda_fp16.h>
#include <cstdint>

// AttentionalPropagation R13: R12 (fp16 tensor cores, 2 CTAs/SM) with the
// epilogue OOB fix — R12 read 8 halves of the fp16 residual but consumed 16,
// adding garbage register data into half of every output row (rel_err 2e3).
//   K0:  x[B,C,L] fp32 -> xT[L,B,C] fp16   (register 4x4 transpose)
//   K12: per-l CTA (128 thr, 101KB smem -> 2 CTAs/SM):
//        pass1 S = qq^T via mma.m16n8k16.f16 (fp32 accum) over 4 rotating
//        fp16 planes; per-chunk smem transpose builds persistent [c][b]
//        planes; softmax verbatim; P->A-frags is pure in-lane half2 packing
//        (m16n8k16 layout, no shuffles); pass2 msg = P q from resident
//        planes; epilogue reads 32B of x fp16 (L2-hot), adds in fp32.
//   K3:  oT[L,B,C] fp32 -> out[B,C,L]      (register 4x4 transpose)

namespace {

constexpr int kB  = 64;
constexpr int kC  = 512;
constexpr int kL  = 4096;
constexpr int kBC = kB * kC;
constexpr int CCH = 32;
constexpr int NCH = kC / CCH;        // 16
constexpr int ROT = 4;               // rotating pass-1 planes

// pass-1 plane: [b][c] fp16, pitch 40 halves (80B) -> fragment LDS conflict-free
constexpr int P1P = 40;
constexpr int P1H = kB * P1P;        // 2560 halves = 5120 B
// pass-2 plane: [c][b] fp16, pitch 72 halves (144B) -> B-frag LDS conflict-free
constexpr int P2P = 72;
constexpr int P2H = CCH * P2P;       // 2304 halves = 4608 B
constexpr int MSGP = 36;             // msg pitch (fp32 words)

constexpr int OFF_ROT  = 0;                        // bytes
constexpr int OFF_PERM = ROT * P1H * 2;            // 20480
constexpr int OFF_MSG  = OFF_PERM + NCH * P2H * 2; // 94208
constexpr int SMEM_K12 = OFF_MSG + kB * MSGP * 4;  // 103424 B -> 2 CTAs/SM

__device__ __half xT_g[(size_t)kL * kBC];          // 256 MB [L][B][C] fp16
__device__ float  oT_g[(size_t)kL * kBC];          // 512 MB [L][B][C] fp32

__device__ __forceinline__ void mma_f16(float d[4],
                                        uint32_t a0, uint32_t a1, uint32_t a2, uint32_t a3,
                                        uint32_t b0, uint32_t b1) {
    asm volatile(
        "mma.sync.aligned.m16n8k16.row.col.f32.f16.f16.f32 "
        "{%0,%1,%2,%3}, {%4,%5,%6,%7}, {%8,%9}, {%0,%1,%2,%3};"
        : "+f"(d[0]), "+f"(d[1]), "+f"(d[2]), "+f"(d[3])
        : "r"(a0), "r"(a1), "r"(a2), "r"(a3), "r"(b0), "r"(b1));
}

__device__ __forceinline__ void cp16(uint32_t dst, const void* src) {
    asm volatile("cp.async.ca.shared.global [%0], [%1], 16;" :: "r"(dst), "l"(src));
}
__device__ __forceinline__ void cp_commit() {
    asm volatile("cp.async.commit_group;" ::: "memory");
}
template <int N>
__device__ __forceinline__ void cp_wait() {
    asm volatile("cp.async.wait_group %0;" :: "n"(N) : "memory");
}
__device__ __forceinline__ void cp_wait_n(int n) {
    switch (n) {
        case 0: cp_wait<0>(); break;  case 1: cp_wait<1>(); break;
        case 2: cp_wait<2>(); break;  default: cp_wait<3>(); break;
    }
}

__device__ __forceinline__ uint32_t lds32(const __half* p) {
    return *reinterpret_cast<const uint32_t*>(p);
}
__device__ __forceinline__ uint32_t h2u(half2 h) {
    return *reinterpret_cast<uint32_t*>(&h);
}

// ---------- K0: x[BC][L] fp32 -> xT[L][BC] fp16 (register transpose) --------
__global__ void __launch_bounds__(256)
k0_transpose(const float* __restrict__ x) {
    const int C0 = blockIdx.x * 64;    // l block
    const int R0 = blockIdx.y * 64;    // bc block
    const int t  = threadIdx.x;
    const int bj = t & 15;
    const int bi = t >> 4;

    const float* sp = x + (size_t)(R0 + 4 * bi) * kL + C0 + 4 * bj;
    const float4 r0 = *(const float4*)sp;
    const float4 r1 = *(const float4*)(sp + kL);
    const float4 r2 = *(const float4*)(sp + 2 * (size_t)kL);
    const float4 r3 = *(const float4*)(sp + 3 * (size_t)kL);

    __half* dp = xT_g + (size_t)(C0 + 4 * bj) * kBC + R0 + 4 * bi;
    #pragma unroll
    for (int k = 0; k < 4; k++) {
        const float v0 = k == 0 ? r0.x : k == 1 ? r0.y : k == 2 ? r0.z : r0.w;
        const float v1 = k == 0 ? r1.x : k == 1 ? r1.y : k == 2 ? r1.z : r1.w;
        const float v2 = k == 0 ? r2.x : k == 1 ? r2.y : k == 2 ? r2.z : r2.w;
        const float v3 = k == 0 ? r3.x : k == 1 ? r3.y : k == 2 ? r3.z : r3.w;
        uint2 pk;
        pk.x = h2u(__floats2half2_rn(v0, v1));
        pk.y = h2u(__floats2half2_rn(v2, v3));
        *reinterpret_cast<uint2*>(dp + (size_t)k * kBC) = pk;
    }
}

// ---------- K3: oT[L][BC] fp32 -> out[BC][L] (register transpose, proven) ---
__global__ void __launch_bounds__(256)
k3_transpose(float* __restrict__ out) {
    const int C0 = blockIdx.x * 64;    // bc block (src cols)
    const int R0 = blockIdx.y * 64;    // l block (src rows)
    const int t  = threadIdx.x;
    const int bj = t & 15;
    const int bi = t >> 4;

    const float* sp = oT_g + (size_t)(R0 + 4 * bi) * kBC + C0 + 4 * bj;
    const float4 r0 = *(const float4*)sp;
    const float4 r1 = *(const float4*)(sp + kBC);
    const float4 r2 = *(const float4*)(sp + 2 * (size_t)kBC);
    const float4 r3 = *(const float4*)(sp + 3 * (size_t)kBC);

    float* dp = out + (size_t)(C0 + 4 * bj) * kL + R0 + 4 * bi;
    *(float4*)dp                    = make_float4(r0.x, r1.x, r2.x, r3.x);
    *(float4*)(dp + kL)             = make_float4(r0.y, r1.y, r2.y, r3.y);
    *(float4*)(dp + 2 * (size_t)kL) = make_float4(r0.z, r1.z, r2.z, r3.z);
    *(float4*)(dp + 3 * (size_t)kL) = make_float4(r0.w, r1.w, r2.w, r3.w);
}

// ====================== K12: fused scores+softmax+apply =====================
__global__ void __launch_bounds__(128)
k12_fused() {
    extern __shared__ __align__(16) char smraw[];
    __half* rot  = reinterpret_cast<__half*>(smraw + OFF_ROT);
    __half* perm = reinterpret_cast<__half*>(smraw + OFF_PERM);
    float*  msg  = reinterpret_cast<float*>(smraw + OFF_MSG);

    const int t = threadIdx.x, lane = t & 31;
    const int strip = t >> 5;              // warp = 16-row strip of S
    const int l = blockIdx.x;
    const int r0 = lane >> 2, q4 = lane & 3;
    const uint32_t smbase = (uint32_t)__cvta_generic_to_shared(smraw);

    // ---- stage chunk ch (64 b x 32 c fp16 = 4KB) into rot[ch&3] ------------
    auto issue = [&](int ch) {
        const int b = t >> 1, h = t & 1;
        const __half* src = xT_g + ((size_t)l * kB + b) * kC + ch * CCH + h * 16;
        const uint32_t dst = smbase + OFF_ROT
                           + (uint32_t)((ch & 3) * P1H + b * P1P + h * 16) * 2u;
        cp16(dst, src);
        cp16(dst + 16u, src + 8);
        cp_commit();
    };

    #pragma unroll
    for (int p = 0; p < ROT; p++) issue(p);

    float acc[8][4];
    #pragma unroll
    for (int j = 0; j < 8; j++)
        #pragma unroll
        for (int i = 0; i < 4; i++) acc[j][i] = 0.0f;

    // -------- Pass 1: S = q q^T, progressive; build [c][b] planes ------------
    #pragma unroll 1
    for (int ch = 0; ch < NCH; ch++) {
        cp_wait_n(min(ROT - 1, NCH - 1 - ch));
        __syncthreads();                   // chunk ch visible; rot[ch&3] owned
        const __half* pl = rot + (ch & 3) * P1H;

        #pragma unroll
        for (int sk = 0; sk < 2; sk++) {   // k = 16 per step
            const __half* ap = pl + (strip * 16 + r0) * P1P + 16 * sk + 2 * q4;
            const uint32_t a0 = lds32(ap);
            const uint32_t a1 = lds32(ap + 8 * P1P);
            const uint32_t a2 = lds32(ap + 8);
            const uint32_t a3 = lds32(ap + 8 * P1P + 8);
            #pragma unroll
            for (int j = 0; j < 8; j++) {
                const __half* bp = pl + (8 * j + r0) * P1P + 16 * sk + 2 * q4;
                mma_f16(acc[j], a0, a1, a2, a3, lds32(bp), lds32(bp + 8));
            }
        }

        // Build perm[ch]: [c][b] from [b][c]. thread: rows {2c2, 2c2+1},
        // b-range 8*bg..+7.
        {
            const int c2 = t & 15, bg = t >> 4;
            uint32_t v[8];
            #pragma unroll
            for (int i = 0; i < 8; i++)
                v[i] = lds32(pl + (8 * bg + i) * P1P + 2 * c2);
            uint32_t lo[4], hi[4];
            #pragma unroll
            for (int i = 0; i < 4; i++) {
                lo[i] = (v[2*i] & 0xffffu) | (v[2*i+1] << 16);
                hi[i] = (v[2*i] >> 16) | (v[2*i+1] & 0xffff0000u);
            }
            uint4* d0 = reinterpret_cast<uint4*>(
                perm + ch * P2H + (2 * c2) * P2P + 8 * bg);
            uint4* d1 = reinterpret_cast<uint4*>(
                perm + ch * P2H + (2 * c2 + 1) * P2P + 8 * bg);
            *d0 = make_uint4(lo[0], lo[1], lo[2], lo[3]);
            *d1 = make_uint4(hi[0], hi[1], hi[2], hi[3]);
        }
        __syncthreads();                   // all reads of rot[ch&3] done
        if (ch + ROT < NCH) issue(ch + ROT);
    }

    // -------- Softmax (verbatim; D-frag layout identical to tf32 path) ------
    {
        const float isc = 0.044194173824159216f;   // 1/sqrt(512)
        #pragma unroll
        for (int hh = 0; hh < 2; hh++) {
            float mx = -1e30f;
            #pragma unroll
            for (int j = 0; j < 8; j++) {
                acc[j][2 * hh]     *= isc;
                acc[j][2 * hh + 1] *= isc;
                mx = fmaxf(mx, fmaxf(acc[j][2 * hh], acc[j][2 * hh + 1]));
            }
            mx = fmaxf(mx, __shfl_xor_sync(0xffffffffu, mx, 1));
            mx = fmaxf(mx, __shfl_xor_sync(0xffffffffu, mx, 2));
            float ssum = 0.0f;
            #pragma unroll
            for (int j = 0; j < 8; j++) {
                const float e0 = __expf(acc[j][2 * hh] - mx);
                const float e1 = __expf(acc[j][2 * hh + 1] - mx);
                acc[j][2 * hh] = e0; acc[j][2 * hh + 1] = e1;
                ssum += e0 + e1;
            }
            ssum += __shfl_xor_sync(0xffffffffu, ssum, 1);
            ssum += __shfl_xor_sync(0xffffffffu, ssum, 2);
            const float inv = 1.0f / ssum;
            #pragma unroll
            for (int j = 0; j < 8; j++) {
                acc[j][2 * hh] *= inv; acc[j][2 * hh + 1] *= inv;
            }
        }
    }

    // -------- P -> f16 A-frags: pure in-lane packing (m16n8k16 layout) ------
    // step sk2 (k = m = 16sk2..+15):
    //   a0 = {P[R][16sk2+2q4], +1}       = h2(acc[2sk2][0],   acc[2sk2][1])
    //   a1 = rows+8                      = h2(acc[2sk2][2],   acc[2sk2][3])
    //   a2 = k+8                         = h2(acc[2sk2+1][0], acc[2sk2+1][1])
    //   a3 = rows+8, k+8                 = h2(acc[2sk2+1][2], acc[2sk2+1][3])
    uint32_t ah[4][4];
    #pragma unroll
    for (int sk2 = 0; sk2 < 4; sk2++) {
        ah[sk2][0] = h2u(__floats2half2_rn(acc[2*sk2][0],   acc[2*sk2][1]));
        ah[sk2][1] = h2u(__floats2half2_rn(acc[2*sk2][2],   acc[2*sk2][3]));
        ah[sk2][2] = h2u(__floats2half2_rn(acc[2*sk2+1][0], acc[2*sk2+1][1]));
        ah[sk2][3] = h2u(__floats2half2_rn(acc[2*sk2+1][2], acc[2*sk2+1][3]));
    }

    // -------- Pass 2: msg = P q from resident [c][b] planes ------------------
    #pragma unroll 1
    for (int ch = 0; ch < NCH; ch++) {
        const __half* pp = perm + ch * P2H;

        float macc[4][4];
        #pragma unroll
        for (int j2 = 0; j2 < 4; j2++)
            #pragma unroll
            for (int i = 0; i < 4; i++) macc[j2][i] = 0.0f;

        #pragma unroll
        for (int sk2 = 0; sk2 < 4; sk2++) {    // k over m = 64
            #pragma unroll
            for (int j2 = 0; j2 < 4; j2++) {   // n over c (4 blocks of 8)
                const __half* bp = pp + (8 * j2 + r0) * P2P + 16 * sk2 + 2 * q4;
                mma_f16(macc[j2], ah[sk2][0], ah[sk2][1], ah[sk2][2], ah[sk2][3],
                        lds32(bp), lds32(bp + 8));
            }
        }

        // msg fragments -> smem [n][c] pitch MSGP (fp32).
        #pragma unroll
        for (int j2 = 0; j2 < 4; j2++) {
            float* mp = msg + (strip * 16 + r0) * MSGP + 8 * j2 + 2 * q4;
            mp[0] = macc[j2][0];            mp[1] = macc[j2][1];
            mp[8 * MSGP] = macc[j2][2];     mp[8 * MSGP + 1] = macc[j2][3];
        }
        __syncthreads();                   // msg visible

        // Epilogue: out = dequant(x fp16, 32B = 16 halves) + msg, fp32 stores.
        {
            const int b = t >> 1, h = t & 1;
            const __half* xp = xT_g + ((size_t)l * kB + b) * kC + ch * CCH + h * 16;
            const uint4 xv0 = reinterpret_cast<const uint4*>(xp)[0];   // c 0..7
            const uint4 xv1 = reinterpret_cast<const uint4*>(xp)[1];   // c 8..15
            const uint32_t xw[8] = {xv0.x, xv0.y, xv0.z, xv0.w,
                                    xv1.x, xv1.y, xv1.z, xv1.w};
            const float* mp = msg + b * MSGP + h * 16;
            float* op = oT_g + ((size_t)l * kB + b) * kC + ch * CCH + h * 16;
            #pragma unroll
            for (int k = 0; k < 4; k++) {
                const float2 xa =
                    __half22float2(*reinterpret_cast<const half2*>(&xw[2 * k]));
                const float2 xb =
                    __half22float2(*reinterpret_cast<const half2*>(&xw[2 * k + 1]));
                ((float4*)op)[k] = make_float4(xa.x + mp[4 * k],
                                               xa.y + mp[4 * k + 1],
                                               xb.x + mp[4 * k + 2],
                                               xb.y + mp[4 * k + 3]);
            }
        }
        __syncthreads();                   // msg drained before next overwrite
    }
}

}  // namespace

extern "C" void kernel_launch(void* const* d_in, const int* in_sizes, int n_in,
                              void* d_out, int out_size) {
    (void)in_sizes; (void)n_in; (void)out_size;
    const float* x = (const float*)d_in[0];
    float* out     = (float*)d_out;

    cudaFuncSetAttribute(k12_fused,
                         cudaFuncAttributeMaxDynamicSharedMemorySize, SMEM_K12);

    dim3 g0(kL / 64, kBC / 64);
    k0_transpose<<<g0, 256>>>(x);
    k12_fused<<<kL, 128, SMEM_K12>>>();
    dim3 g3(kBC / 64, kL / 64);
    k3_transpose<<<g3, 256>>>(out);
}

// round 15
// speedup vs baseline: 1.4994x; 1.3741x over previous
#include <cuda_runtime.h>
#include <cuda_fp16.h>
#include <cstdint>

// AttentionalPropagation R15: R13 core (fp16 mma, 2 CTAs/SM, 757us) with the
// transpose granule fix + fp16 oT.
//   K0:  x[B,C,L] fp32 -> xT[L,B,C] fp16.  8(bc)x4(l) thread blocks: loads are
//        8x64B runs, stores are 4x128B contiguous runs (R13's 8B-granule
//        stores ran at 25% sector utilization -> 227us).
//   K12: unchanged mma/softmax/pass2 (fp16 m16n8k16, in-lane P->A packing);
//        epilogue now stores oT fp16 (halves write traffic; adds only output
//        quantization ~2.8e-4 RMS).
//   K3:  oT fp16 -> out fp32, exact mirror of new K0.

namespace {

constexpr int kB  = 64;
constexpr int kC  = 512;
constexpr int kL  = 4096;
constexpr int kBC = kB * kC;
constexpr int CCH = 32;
constexpr int NCH = kC / CCH;        // 16
constexpr int ROT = 4;               // rotating pass-1 planes

constexpr int P1P = 40;              // pass-1 plane pitch (halves)
constexpr int P1H = kB * P1P;        // 2560 halves
constexpr int P2P = 72;              // pass-2 [c][b] plane pitch (halves)
constexpr int P2H = CCH * P2P;       // 2304 halves
constexpr int MSGP = 36;             // msg pitch (fp32 words)

constexpr int OFF_ROT  = 0;
constexpr int OFF_PERM = ROT * P1H * 2;            // 20480
constexpr int OFF_MSG  = OFF_PERM + NCH * P2H * 2; // 94208
constexpr int SMEM_K12 = OFF_MSG + kB * MSGP * 4;  // 103424 B -> 2 CTAs/SM

__device__ __half xT_g[(size_t)kL * kBC];          // 256 MB [L][B][C] fp16
__device__ __half oT_g[(size_t)kL * kBC];          // 256 MB [L][B][C] fp16

__device__ __forceinline__ void mma_f16(float d[4],
                                        uint32_t a0, uint32_t a1, uint32_t a2, uint32_t a3,
                                        uint32_t b0, uint32_t b1) {
    asm volatile(
        "mma.sync.aligned.m16n8k16.row.col.f32.f16.f16.f32 "
        "{%0,%1,%2,%3}, {%4,%5,%6,%7}, {%8,%9}, {%0,%1,%2,%3};"
        : "+f"(d[0]), "+f"(d[1]), "+f"(d[2]), "+f"(d[3])
        : "r"(a0), "r"(a1), "r"(a2), "r"(a3), "r"(b0), "r"(b1));
}

__device__ __forceinline__ void cp16(uint32_t dst, const void* src) {
    asm volatile("cp.async.ca.shared.global [%0], [%1], 16;" :: "r"(dst), "l"(src));
}
__device__ __forceinline__ void cp_commit() {
    asm volatile("cp.async.commit_group;" ::: "memory");
}
template <int N>
__device__ __forceinline__ void cp_wait() {
    asm volatile("cp.async.wait_group %0;" :: "n"(N) : "memory");
}
__device__ __forceinline__ void cp_wait_n(int n) {
    switch (n) {
        case 0: cp_wait<0>(); break;  case 1: cp_wait<1>(); break;
        case 2: cp_wait<2>(); break;  default: cp_wait<3>(); break;
    }
}

__device__ __forceinline__ uint32_t lds32(const __half* p) {
    return *reinterpret_cast<const uint32_t*>(p);
}
__device__ __forceinline__ uint32_t h2u(half2 h) {
    return *reinterpret_cast<uint32_t*>(&h);
}

// ---- K0: x[BC][L] fp32 -> xT[L][BC] fp16. Tile 64bc x 128l, 256 thr. -------
// bc8 = t&7 (8 bc-blocks of 8), lb = t>>3 (32 l-blocks of 4).
// Loads: 8 x (8 lanes x 64B runs). Stores: 4 x (128B contiguous runs).
__global__ void __launch_bounds__(256)
k0_transpose(const float* __restrict__ x) {
    const int C0 = blockIdx.x * 128;   // l block
    const int R0 = blockIdx.y * 64;    // bc block
    const int t  = threadIdx.x;
    const int bc8 = t & 7;
    const int lb  = t >> 3;

    float4 r[8];
    #pragma unroll
    for (int i = 0; i < 8; i++)
        r[i] = *(const float4*)(x + (size_t)(R0 + 8 * bc8 + i) * kL + C0 + 4 * lb);

    // For each of 4 l's, pack 8 bc values into 8 halves (16B).
    #pragma unroll
    for (int k = 0; k < 4; k++) {
        float v[8];
        #pragma unroll
        for (int i = 0; i < 8; i++)
            v[i] = k == 0 ? r[i].x : k == 1 ? r[i].y : k == 2 ? r[i].z : r[i].w;
        uint4 pk;
        pk.x = h2u(__floats2half2_rn(v[0], v[1]));
        pk.y = h2u(__floats2half2_rn(v[2], v[3]));
        pk.z = h2u(__floats2half2_rn(v[4], v[5]));
        pk.w = h2u(__floats2half2_rn(v[6], v[7]));
        *reinterpret_cast<uint4*>(
            xT_g + (size_t)(C0 + 4 * lb + k) * kBC + R0 + 8 * bc8) = pk;
    }
}

// ---- K3: oT[L][BC] fp16 -> out[BC][L] fp32. Mirror of K0. ------------------
__global__ void __launch_bounds__(256)
k3_transpose(float* __restrict__ out) {
    const int C0 = blockIdx.x * 128;   // l block
    const int R0 = blockIdx.y * 64;    // bc block
    const int t  = threadIdx.x;
    const int bc8 = t & 7;
    const int lb  = t >> 3;

    uint4 rv[4];
    #pragma unroll
    for (int k = 0; k < 4; k++)
        rv[k] = *reinterpret_cast<const uint4*>(
            oT_g + (size_t)(C0 + 4 * lb + k) * kBC + R0 + 8 * bc8);

    #pragma unroll
    for (int i = 0; i < 8; i++) {
        float o[4];
        #pragma unroll
        for (int k = 0; k < 4; k++) {
            const uint32_t w = i < 2 ? rv[k].x : i < 4 ? rv[k].y
                             : i < 6 ? rv[k].z : rv[k].w;
            const float2 f2 = __half22float2(*reinterpret_cast<const half2*>(&w));
            o[k] = (i & 1) ? f2.y : f2.x;
        }
        *(float4*)(out + (size_t)(R0 + 8 * bc8 + i) * kL + C0 + 4 * lb) =
            make_float4(o[0], o[1], o[2], o[3]);
    }
}

// ====================== K12: fused scores+softmax+apply =====================
__global__ void __launch_bounds__(128)
k12_fused() {
    extern __shared__ __align__(16) char smraw[];
    __half* rot  = reinterpret_cast<__half*>(smraw + OFF_ROT);
    __half* perm = reinterpret_cast<__half*>(smraw + OFF_PERM);
    float*  msg  = reinterpret_cast<float*>(smraw + OFF_MSG);

    const int t = threadIdx.x, lane = t & 31;
    const int strip = t >> 5;              // warp = 16-row strip of S
    const int l = blockIdx.x;
    const int r0 = lane >> 2, q4 = lane & 3;
    const uint32_t smbase = (uint32_t)__cvta_generic_to_shared(smraw);

    auto issue = [&](int ch) {
        const int b = t >> 1, h = t & 1;
        const __half* src = xT_g + ((size_t)l * kB + b) * kC + ch * CCH + h * 16;
        const uint32_t dst = smbase + OFF_ROT
                           + (uint32_t)((ch & 3) * P1H + b * P1P + h * 16) * 2u;
        cp16(dst, src);
        cp16(dst + 16u, src + 8);
        cp_commit();
    };

    #pragma unroll
    for (int p = 0; p < ROT; p++) issue(p);

    float acc[8][4];
    #pragma unroll
    for (int j = 0; j < 8; j++)
        #pragma unroll
        for (int i = 0; i < 4; i++) acc[j][i] = 0.0f;

    // -------- Pass 1: S = q q^T, progressive; build [c][b] planes ------------
    #pragma unroll 1
    for (int ch = 0; ch < NCH; ch++) {
        cp_wait_n(min(ROT - 1, NCH - 1 - ch));
        __syncthreads();
        const __half* pl = rot + (ch & 3) * P1H;

        #pragma unroll
        for (int sk = 0; sk < 2; sk++) {
            const __half* ap = pl + (strip * 16 + r0) * P1P + 16 * sk + 2 * q4;
            const uint32_t a0 = lds32(ap);
            const uint32_t a1 = lds32(ap + 8 * P1P);
            const uint32_t a2 = lds32(ap + 8);
            const uint32_t a3 = lds32(ap + 8 * P1P + 8);
            #pragma unroll
            for (int j = 0; j < 8; j++) {
                const __half* bp = pl + (8 * j + r0) * P1P + 16 * sk + 2 * q4;
                mma_f16(acc[j], a0, a1, a2, a3, lds32(bp), lds32(bp + 8));
            }
        }

        // Build perm[ch]: [c][b] from [b][c].
        {
            const int c2 = t & 15, bg = t >> 4;
            uint32_t v[8];
            #pragma unroll
            for (int i = 0; i < 8; i++)
                v[i] = lds32(pl + (8 * bg + i) * P1P + 2 * c2);
            uint32_t lo[4], hi[4];
            #pragma unroll
            for (int i = 0; i < 4; i++) {
                lo[i] = (v[2*i] & 0xffffu) | (v[2*i+1] << 16);
                hi[i] = (v[2*i] >> 16) | (v[2*i+1] & 0xffff0000u);
            }
            uint4* d0 = reinterpret_cast<uint4*>(
                perm + ch * P2H + (2 * c2) * P2P + 8 * bg);
            uint4* d1 = reinterpret_cast<uint4*>(
                perm + ch * P2H + (2 * c2 + 1) * P2P + 8 * bg);
            *d0 = make_uint4(lo[0], lo[1], lo[2], lo[3]);
            *d1 = make_uint4(hi[0], hi[1], hi[2], hi[3]);
        }
        __syncthreads();
        if (ch + ROT < NCH) issue(ch + ROT);
    }

    // -------- Softmax (verbatim) ---------------------------------------------
    {
        const float isc = 0.044194173824159216f;   // 1/sqrt(512)
        #pragma unroll
        for (int hh = 0; hh < 2; hh++) {
            float mx = -1e30f;
            #pragma unroll
            for (int j = 0; j < 8; j++) {
                acc[j][2 * hh]     *= isc;
                acc[j][2 * hh + 1] *= isc;
                mx = fmaxf(mx, fmaxf(acc[j][2 * hh], acc[j][2 * hh + 1]));
            }
            mx = fmaxf(mx, __shfl_xor_sync(0xffffffffu, mx, 1));
            mx = fmaxf(mx, __shfl_xor_sync(0xffffffffu, mx, 2));
            float ssum = 0.0f;
            #pragma unroll
            for (int j = 0; j < 8; j++) {
                const float e0 = __expf(acc[j][2 * hh] - mx);
                const float e1 = __expf(acc[j][2 * hh + 1] - mx);
                acc[j][2 * hh] = e0; acc[j][2 * hh + 1] = e1;
                ssum += e0 + e1;
            }
            ssum += __shfl_xor_sync(0xffffffffu, ssum, 1);
            ssum += __shfl_xor_sync(0xffffffffu, ssum, 2);
            const float inv = 1.0f / ssum;
            #pragma unroll
            for (int j = 0; j < 8; j++) {
                acc[j][2 * hh] *= inv; acc[j][2 * hh + 1] *= inv;
            }
        }
    }

    // -------- P -> f16 A-frags (in-lane packing, verified R13) --------------
    uint32_t ah[4][4];
    #pragma unroll
    for (int sk2 = 0; sk2 < 4; sk2++) {
        ah[sk2][0] = h2u(__floats2half2_rn(acc[2*sk2][0],   acc[2*sk2][1]));
        ah[sk2][1] = h2u(__floats2half2_rn(acc[2*sk2][2],   acc[2*sk2][3]));
        ah[sk2][2] = h2u(__floats2half2_rn(acc[2*sk2+1][0], acc[2*sk2+1][1]));
        ah[sk2][3] = h2u(__floats2half2_rn(acc[2*sk2+1][2], acc[2*sk2+1][3]));
    }

    // -------- Pass 2: msg = P q; epilogue stores oT fp16 ---------------------
    #pragma unroll 1
    for (int ch = 0; ch < NCH; ch++) {
        const __half* pp = perm + ch * P2H;

        float macc[4][4];
        #pragma unroll
        for (int j2 = 0; j2 < 4; j2++)
            #pragma unroll
            for (int i = 0; i < 4; i++) macc[j2][i] = 0.0f;

        #pragma unroll
        for (int sk2 = 0; sk2 < 4; sk2++) {
            #pragma unroll
            for (int j2 = 0; j2 < 4; j2++) {
                const __half* bp = pp + (8 * j2 + r0) * P2P + 16 * sk2 + 2 * q4;
                mma_f16(macc[j2], ah[sk2][0], ah[sk2][1], ah[sk2][2], ah[sk2][3],
                        lds32(bp), lds32(bp + 8));
            }
        }

        #pragma unroll
        for (int j2 = 0; j2 < 4; j2++) {
            float* mp = msg + (strip * 16 + r0) * MSGP + 8 * j2 + 2 * q4;
            mp[0] = macc[j2][0];            mp[1] = macc[j2][1];
            mp[8 * MSGP] = macc[j2][2];     mp[8 * MSGP + 1] = macc[j2][3];
        }
        __syncthreads();

        // Epilogue: oT = fp16(x + msg), 32B fp16 stores.
        {
            const int b = t >> 1, h = t & 1;
            const __half* xp = xT_g + ((size_t)l * kB + b) * kC + ch * CCH + h * 16;
            const uint4 xv0 = reinterpret_cast<const uint4*>(xp)[0];
            const uint4 xv1 = reinterpret_cast<const uint4*>(xp)[1];
            const uint32_t xw[8] = {xv0.x, xv0.y, xv0.z, xv0.w,
                                    xv1.x, xv1.y, xv1.z, xv1.w};
            const float* mp = msg + b * MSGP + h * 16;
            __half* op = oT_g + ((size_t)l * kB + b) * kC + ch * CCH + h * 16;
            uint32_t ow[8];
            #pragma unroll
            for (int k = 0; k < 8; k++) {
                const float2 xf =
                    __half22float2(*reinterpret_cast<const half2*>(&xw[k]));
                ow[k] = h2u(__floats2half2_rn(xf.x + mp[2 * k],
                                              xf.y + mp[2 * k + 1]));
            }
            reinterpret_cast<uint4*>(op)[0] = make_uint4(ow[0], ow[1], ow[2], ow[3]);
            reinterpret_cast<uint4*>(op)[1] = make_uint4(ow[4], ow[5], ow[6], ow[7]);
        }
        __syncthreads();
    }
}

}  // namespace

extern "C" void kernel_launch(void* const* d_in, const int* in_sizes, int n_in,
                              void* d_out, int out_size) {
    (void)in_sizes; (void)n_in; (void)out_size;
    const float* x = (const float*)d_in[0];
    float* out     = (float*)d_out;

    cudaFuncSetAttribute(k12_fused,
                         cudaFuncAttributeMaxDynamicSharedMemorySize, SMEM_K12);

    dim3 gt(kL / 128, kBC / 64);       // 32 x 512
    k0_transpose<<<gt, 256>>>(x);
    k12_fused<<<kL, 128, SMEM_K12>>>();
    k3_transpose<<<gt, 256>>>(out);
}

// round 16
// speedup vs baseline: 1.7268x; 1.1517x over previous
#include <cuda_runtime.h>
#include <cuda_fp16.h>
#include <cstdint>

// AttentionalPropagation R16: ldmatrix + single swizzled layout, 3 CTAs/SM.
//   K0:  x[B,C,L] fp32 -> xT[L,B,C] fp16   (R15 transpose, 6.1 TB/s, verbatim)
//   K12: per-l CTA (128 thr, 70.7KB smem -> 3 CTAs/SM = 12 warps):
//        all 16 c-chunk planes (4KB each, XOR-swizzled [b][c]) staged once via
//        cp.async and kept resident. Pass-1 fragments via ldmatrix.x4 (A+B);
//        pass-2 B via ldmatrix.x4.trans from the SAME planes (perm planes and
//        their build phase eliminated). Softmax + in-lane P->A fp16 packing
//        verbatim (locked numerics). msg fp16; epilogue reads x from the
//        resident plane and stores oT fp16 via __hadd2.
//   K3:  oT fp16 -> out fp32               (R15 transpose, verbatim)

namespace {

constexpr int kB  = 64;
constexpr int kC  = 512;
constexpr int kL  = 4096;
constexpr int kBC = kB * kC;
constexpr int CCH = 32;
constexpr int NCH = kC / CCH;        // 16

// Chunk plane: 64 b-rows x 32 c-halves = 64B/row, 4KB/plane. XOR swizzle:
// granule (16B) index g stored at g ^ ((b>>1)&3)  -> conflict-free for
// ldmatrix (8 rows, fixed g), ldmatrix.trans, cp.async and epilogue reads.
constexpr int PLANE_B = 4096;        // bytes per plane
constexpr int MSGP    = 40;          // msg pitch (halves); 80B rows, 16B-aligned
constexpr int OFF_MSG = NCH * PLANE_B;              // 65536
constexpr int SMEM_K12 = OFF_MSG + kB * MSGP * 2;   // 70656 B -> 3 CTAs/SM

__device__ __half xT_g[(size_t)kL * kBC];           // 256 MB [L][B][C] fp16
__device__ __half oT_g[(size_t)kL * kBC];           // 256 MB [L][B][C] fp16

__device__ __forceinline__ void mma_f16(float d[4],
                                        uint32_t a0, uint32_t a1, uint32_t a2, uint32_t a3,
                                        uint32_t b0, uint32_t b1) {
    asm volatile(
        "mma.sync.aligned.m16n8k16.row.col.f32.f16.f16.f32 "
        "{%0,%1,%2,%3}, {%4,%5,%6,%7}, {%8,%9}, {%0,%1,%2,%3};"
        : "+f"(d[0]), "+f"(d[1]), "+f"(d[2]), "+f"(d[3])
        : "r"(a0), "r"(a1), "r"(a2), "r"(a3), "r"(b0), "r"(b1));
}

__device__ __forceinline__ void ldsm_x4(uint32_t& r0, uint32_t& r1,
                                        uint32_t& r2, uint32_t& r3, uint32_t addr) {
    asm volatile("ldmatrix.sync.aligned.m8n8.x4.shared.b16 {%0,%1,%2,%3}, [%4];"
                 : "=r"(r0), "=r"(r1), "=r"(r2), "=r"(r3) : "r"(addr));
}
__device__ __forceinline__ void ldsm_x4_t(uint32_t& r0, uint32_t& r1,
                                          uint32_t& r2, uint32_t& r3, uint32_t addr) {
    asm volatile("ldmatrix.sync.aligned.m8n8.x4.trans.shared.b16 {%0,%1,%2,%3}, [%4];"
                 : "=r"(r0), "=r"(r1), "=r"(r2), "=r"(r3) : "r"(addr));
}

__device__ __forceinline__ void cp16(uint32_t dst, const void* src) {
    asm volatile("cp.async.ca.shared.global [%0], [%1], 16;" :: "r"(dst), "l"(src));
}
__device__ __forceinline__ void cp_commit() {
    asm volatile("cp.async.commit_group;" ::: "memory");
}
template <int N>
__device__ __forceinline__ void cp_wait() {
    asm volatile("cp.async.wait_group %0;" :: "n"(N) : "memory");
}
__device__ __forceinline__ void cp_wait_n(int n) {   // constant-folded call sites
    switch (n) {
        case 0:  cp_wait<0>();  break;  case 1:  cp_wait<1>();  break;
        case 2:  cp_wait<2>();  break;  case 3:  cp_wait<3>();  break;
        case 4:  cp_wait<4>();  break;  case 5:  cp_wait<5>();  break;
        case 6:  cp_wait<6>();  break;  case 7:  cp_wait<7>();  break;
        case 8:  cp_wait<8>();  break;  case 9:  cp_wait<9>();  break;
        case 10: cp_wait<10>(); break;  case 11: cp_wait<11>(); break;
        case 12: cp_wait<12>(); break;  case 13: cp_wait<13>(); break;
        case 14: cp_wait<14>(); break;  default: cp_wait<15>(); break;
    }
}

__device__ __forceinline__ uint32_t h2u(half2 h) {
    return *reinterpret_cast<uint32_t*>(&h);
}

// ---- K0: x[BC][L] fp32 -> xT[L][BC] fp16 (R15, verbatim) -------------------
__global__ void __launch_bounds__(256)
k0_transpose(const float* __restrict__ x) {
    const int C0 = blockIdx.x * 128;
    const int R0 = blockIdx.y * 64;
    const int t  = threadIdx.x;
    const int bc8 = t & 7;
    const int lb  = t >> 3;

    float4 r[8];
    #pragma unroll
    for (int i = 0; i < 8; i++)
        r[i] = *(const float4*)(x + (size_t)(R0 + 8 * bc8 + i) * kL + C0 + 4 * lb);

    #pragma unroll
    for (int k = 0; k < 4; k++) {
        float v[8];
        #pragma unroll
        for (int i = 0; i < 8; i++)
            v[i] = k == 0 ? r[i].x : k == 1 ? r[i].y : k == 2 ? r[i].z : r[i].w;
        uint4 pk;
        pk.x = h2u(__floats2half2_rn(v[0], v[1]));
        pk.y = h2u(__floats2half2_rn(v[2], v[3]));
        pk.z = h2u(__floats2half2_rn(v[4], v[5]));
        pk.w = h2u(__floats2half2_rn(v[6], v[7]));
        *reinterpret_cast<uint4*>(
            xT_g + (size_t)(C0 + 4 * lb + k) * kBC + R0 + 8 * bc8) = pk;
    }
}

// ---- K3: oT[L][BC] fp16 -> out[BC][L] fp32 (R15, verbatim) -----------------
__global__ void __launch_bounds__(256)
k3_transpose(float* __restrict__ out) {
    const int C0 = blockIdx.x * 128;
    const int R0 = blockIdx.y * 64;
    const int t  = threadIdx.x;
    const int bc8 = t & 7;
    const int lb  = t >> 3;

    uint4 rv[4];
    #pragma unroll
    for (int k = 0; k < 4; k++)
        rv[k] = *reinterpret_cast<const uint4*>(
            oT_g + (size_t)(C0 + 4 * lb + k) * kBC + R0 + 8 * bc8);

    #pragma unroll
    for (int i = 0; i < 8; i++) {
        float o[4];
        #pragma unroll
        for (int k = 0; k < 4; k++) {
            const uint32_t w = i < 2 ? rv[k].x : i < 4 ? rv[k].y
                             : i < 6 ? rv[k].z : rv[k].w;
            const float2 f2 = __half22float2(*reinterpret_cast<const half2*>(&w));
            o[k] = (i & 1) ? f2.y : f2.x;
        }
        *(float4*)(out + (size_t)(R0 + 8 * bc8 + i) * kL + C0 + 4 * lb) =
            make_float4(o[0], o[1], o[2], o[3]);
    }
}

// ====================== K12: fused scores+softmax+apply =====================
__global__ void __launch_bounds__(128)
k12_fused() {
    extern __shared__ __align__(16) char smraw[];
    __half* msg = reinterpret_cast<__half*>(smraw + OFF_MSG);

    const int t = threadIdx.x, lane = t & 31;
    const int strip = t >> 5;              // warp = 16-row strip of S
    const int l = blockIdx.x;
    const int r0 = lane >> 2, q4 = lane & 3;
    const uint32_t smb = (uint32_t)__cvta_generic_to_shared(smraw);

    // ---- stage all 16 chunk planes (2 cp16/thread/chunk, 16 groups) --------
    {
        const int b = t >> 1, h = t & 1;
        const int bx = (b >> 1) & 3;                       // swizzle key
        const __half* src0 = xT_g + ((size_t)l * kB + b) * kC;
        #pragma unroll
        for (int ch = 0; ch < NCH; ch++) {
            #pragma unroll
            for (int i = 0; i < 2; i++) {
                const int g = 2 * h + i;
                cp16(smb + (uint32_t)(ch * PLANE_B + b * 64 + ((g ^ bx) << 4)),
                     src0 + ch * CCH + g * 8);
            }
            cp_commit();
        }
    }

    // ---- lane-invariant ldmatrix address components -------------------------
    const int mat = lane >> 3, l8 = lane & 7;
    // pass-1 A: row = strip*16 + (mat&1)*8 + l8 ; granule = 2sk + (mat>>1)
    const int a_row = strip * 16 + ((mat & 1) << 3) + l8;
    const int a_gs  = mat >> 1;
    const int a_xr  = (a_row >> 1) & 3;
    // pass-1 B: n-row = 16jj + (mat>>1)*8 + l8 ; granule = 2sk + (mat&1)
    const int b_nb  = ((mat >> 1) << 3) + l8;
    const int b_gs  = mat & 1;
    // pass-2 Bt: k-row = 16sk2 + (mat&1)*8 + l8 ; granule = 2jj2 + (mat>>1)
    const int t_kb  = ((mat & 1) << 3) + l8;
    const int t_gs  = mat >> 1;

    float acc[8][4];
    #pragma unroll
    for (int j = 0; j < 8; j++)
        #pragma unroll
        for (int i = 0; i < 4; i++) acc[j][i] = 0.0f;

    // -------- Pass 1: S = q q^T, progressive over arriving planes ------------
    #pragma unroll 1
    for (int ch = 0; ch < NCH; ch++) {
        cp_wait_n(NCH - 1 - ch);
        __syncthreads();                   // plane ch visible to all warps
        const uint32_t pl = smb + (uint32_t)(ch * PLANE_B);
        #pragma unroll
        for (int sk = 0; sk < 2; sk++) {
            uint32_t a0, a1, a2, a3;
            ldsm_x4(a0, a1, a2, a3,
                    pl + a_row * 64 + (((2 * sk + a_gs) ^ a_xr) << 4));
            #pragma unroll
            for (int jj = 0; jj < 4; jj++) {
                const int nrow = 16 * jj + b_nb;
                uint32_t b00, b01, b10, b11;
                ldsm_x4(b00, b01, b10, b11,
                        pl + nrow * 64 +
                        (((2 * sk + b_gs) ^ ((nrow >> 1) & 3)) << 4));
                mma_f16(acc[2 * jj],     a0, a1, a2, a3, b00, b01);
                mma_f16(acc[2 * jj + 1], a0, a1, a2, a3, b10, b11);
            }
        }
    }

    // -------- Softmax (verbatim) ---------------------------------------------
    {
        const float isc = 0.044194173824159216f;   // 1/sqrt(512)
        #pragma unroll
        for (int hh = 0; hh < 2; hh++) {
            float mx = -1e30f;
            #pragma unroll
            for (int j = 0; j < 8; j++) {
                acc[j][2 * hh]     *= isc;
                acc[j][2 * hh + 1] *= isc;
                mx = fmaxf(mx, fmaxf(acc[j][2 * hh], acc[j][2 * hh + 1]));
            }
            mx = fmaxf(mx, __shfl_xor_sync(0xffffffffu, mx, 1));
            mx = fmaxf(mx, __shfl_xor_sync(0xffffffffu, mx, 2));
            float ssum = 0.0f;
            #pragma unroll
            for (int j = 0; j < 8; j++) {
                const float e0 = __expf(acc[j][2 * hh] - mx);
                const float e1 = __expf(acc[j][2 * hh + 1] - mx);
                acc[j][2 * hh] = e0; acc[j][2 * hh + 1] = e1;
                ssum += e0 + e1;
            }
            ssum += __shfl_xor_sync(0xffffffffu, ssum, 1);
            ssum += __shfl_xor_sync(0xffffffffu, ssum, 2);
            const float inv = 1.0f / ssum;
            #pragma unroll
            for (int j = 0; j < 8; j++) {
                acc[j][2 * hh] *= inv; acc[j][2 * hh + 1] *= inv;
            }
        }
    }

    // -------- P -> f16 A-frags (in-lane packing, verified R13/R15) ----------
    uint32_t ah[4][4];
    #pragma unroll
    for (int sk2 = 0; sk2 < 4; sk2++) {
        ah[sk2][0] = h2u(__floats2half2_rn(acc[2*sk2][0],   acc[2*sk2][1]));
        ah[sk2][1] = h2u(__floats2half2_rn(acc[2*sk2][2],   acc[2*sk2][3]));
        ah[sk2][2] = h2u(__floats2half2_rn(acc[2*sk2+1][0], acc[2*sk2+1][1]));
        ah[sk2][3] = h2u(__floats2half2_rn(acc[2*sk2+1][2], acc[2*sk2+1][3]));
    }

    // -------- Pass 2: msg = P q via ldmatrix.trans from resident planes -----
    #pragma unroll 1
    for (int ch = 0; ch < NCH; ch++) {
        const uint32_t pl = smb + (uint32_t)(ch * PLANE_B);

        float macc[4][4];
        #pragma unroll
        for (int j2 = 0; j2 < 4; j2++)
            #pragma unroll
            for (int i = 0; i < 4; i++) macc[j2][i] = 0.0f;

        #pragma unroll
        for (int sk2 = 0; sk2 < 4; sk2++) {       // k over m = 64
            const int krow = 16 * sk2 + t_kb;
            const int kxr  = (krow >> 1) & 3;
            #pragma unroll
            for (int jj2 = 0; jj2 < 2; jj2++) {   // c-granule pairs
                uint32_t c00, c01, c10, c11;
                ldsm_x4_t(c00, c01, c10, c11,
                          pl + krow * 64 + (((2 * jj2 + t_gs) ^ kxr) << 4));
                mma_f16(macc[2 * jj2],     ah[sk2][0], ah[sk2][1],
                        ah[sk2][2], ah[sk2][3], c00, c01);
                mma_f16(macc[2 * jj2 + 1], ah[sk2][0], ah[sk2][1],
                        ah[sk2][2], ah[sk2][3], c10, c11);
            }
        }

        // msg fragments -> fp16 smem [n][c] pitch MSGP halves.
        #pragma unroll
        for (int j2 = 0; j2 < 4; j2++) {
            __half* mp = msg + (strip * 16 + r0) * MSGP + 8 * j2 + 2 * q4;
            *reinterpret_cast<half2*>(mp) =
                __floats2half2_rn(macc[j2][0], macc[j2][1]);
            *reinterpret_cast<half2*>(mp + 8 * MSGP) =
                __floats2half2_rn(macc[j2][2], macc[j2][3]);
        }
        __syncthreads();                   // msg visible

        // Epilogue: oT = x (from resident plane) + msg, fp16, 32B stores.
        {
            const int b = t >> 1, h = t & 1;
            const int bx = (b >> 1) & 3;
            const __half* plh = reinterpret_cast<const __half*>(smraw)
                              + ch * (PLANE_B / 2) + b * 32;
            uint4 xv[2];
            #pragma unroll
            for (int i = 0; i < 2; i++) {
                const int g = 2 * h + i;
                xv[i] = *reinterpret_cast<const uint4*>(plh + ((g ^ bx) << 3));
            }
            const uint4 mv0 = reinterpret_cast<const uint4*>(msg + b * MSGP + h * 16)[0];
            const uint4 mv1 = reinterpret_cast<const uint4*>(msg + b * MSGP + h * 16)[1];
            const uint32_t xw[8] = {xv[0].x, xv[0].y, xv[0].z, xv[0].w,
                                    xv[1].x, xv[1].y, xv[1].z, xv[1].w};
            const uint32_t mw[8] = {mv0.x, mv0.y, mv0.z, mv0.w,
                                    mv1.x, mv1.y, mv1.z, mv1.w};
            uint32_t ow[8];
            #pragma unroll
            for (int k = 0; k < 8; k++) {
                const half2 xh = *reinterpret_cast<const half2*>(&xw[k]);
                const half2 mh = *reinterpret_cast<const half2*>(&mw[k]);
                ow[k] = h2u(__hadd2(xh, mh));
            }
            __half* op = oT_g + ((size_t)l * kB + b) * kC + ch * CCH + h * 16;
            reinterpret_cast<uint4*>(op)[0] = make_uint4(ow[0], ow[1], ow[2], ow[3]);
            reinterpret_cast<uint4*>(op)[1] = make_uint4(ow[4], ow[5], ow[6], ow[7]);
        }
        __syncthreads();                   // msg drained before next overwrite
    }
}

}  // namespace

extern "C" void kernel_launch(void* const* d_in, const int* in_sizes, int n_in,
                              void* d_out, int out_size) {
    (void)in_sizes; (void)n_in; (void)out_size;
    const float* x = (const float*)d_in[0];
    float* out     = (float*)d_out;

    cudaFuncSetAttribute(k12_fused,
                         cudaFuncAttributeMaxDynamicSharedMemorySize, SMEM_K12);

    dim3 gt(kL / 128, kBC / 64);       // 32 x 512
    k0_transpose<<<gt, 256>>>(x);
    k12_fused<<<kL, 128, SMEM_K12>>>();
    k3_transpose<<<gt, 256>>>(out);
}